// round 8
// baseline (speedup 1.0000x reference)
#include <cuda_runtime.h>
#include <cuda_fp16.h>
#include <cstdint>
#include <math.h>

#define B_  2
#define H2_ 16
#define H_  8
#define S_  2048
#define D_  128
#define BQ  128
#define BK  64
#define NT  256

// smem layout in __half units (2-stage double buffer)
#define KPITCH 136                 // 272 B/row; ldmatrix conflict-free
#define VPITCH 72                  // 144 B/row
#define KSTRIDE (64 * KPITCH)      // 8704 halves
#define VROWS  136                 // 128 data rows + ones row (128) + zeros (129-135)
#define VSTRIDE (VROWS * VPITCH)   // 9792 halves
#define OFF_K  0
#define OFF_V  (2 * KSTRIDE)       // 17408
#define SMH    (OFF_V + 2 * VSTRIDE)  // 36992 halves = 73984 B

// device scratch
__device__ float   g_o[(size_t)B_ * H2_ * S_ * D_];
__device__ __half  g_qh[(size_t)B_ * H2_ * S_ * D_];
__device__ __half  g_kh[(size_t)B_ * H2_ * S_ * D_];
__device__ __half  g_vth[(size_t)B_ * H_ * D_ * S_];
__device__ double2 g_part[16 * 32];
__device__ float2  g_stats[16];
__device__ float   g_lam;

__device__ __forceinline__ uint32_t smem_u32(const void* p) {
    uint32_t a;
    asm("{ .reg .u64 t; cvta.to.shared.u64 t, %1; cvt.u32.u64 %0, t; }" : "=r"(a) : "l"(p));
    return a;
}

#define CP16(dst, src) \
    asm volatile("cp.async.cg.shared.global [%0], [%1], 16;" :: "r"(dst), "l"(src))
#define CP_COMMIT() asm volatile("cp.async.commit_group;" ::: "memory")
#define CP_WAIT(n)  asm volatile("cp.async.wait_group %0;" :: "n"(n) : "memory")

#define LDSM4(r0, r1, r2, r3, a) \
    asm volatile("ldmatrix.sync.aligned.m8n8.x4.shared.b16 {%0,%1,%2,%3}, [%4];" \
        : "=r"(r0), "=r"(r1), "=r"(r2), "=r"(r3) : "r"(a))
#define LDSM2(r0, r1, a) \
    asm volatile("ldmatrix.sync.aligned.m8n8.x2.shared.b16 {%0,%1}, [%2];" \
        : "=r"(r0), "=r"(r1) : "r"(a))

__device__ __forceinline__ void mma16(float c[4], uint32_t a0, uint32_t a1,
                                      uint32_t a2, uint32_t a3,
                                      uint32_t b0, uint32_t b1) {
    asm volatile(
        "mma.sync.aligned.m16n8k16.row.col.f32.f16.f16.f32 "
        "{%0,%1,%2,%3}, {%4,%5,%6,%7}, {%8,%9}, {%0,%1,%2,%3};"
        : "+f"(c[0]), "+f"(c[1]), "+f"(c[2]), "+f"(c[3])
        : "r"(a0), "r"(a1), "r"(a2), "r"(a3), "r"(b0), "r"(b1));
}

__device__ __forceinline__ uint32_t pack2(float lo, float hi) {
    __half2 h = __floats2half2_rn(lo, hi);
    return *(uint32_t*)&h;
}
__device__ __forceinline__ uint32_t h2exp2(uint32_t x) {
    uint32_t r;
    asm("ex2.approx.f16x2 %0, %1;" : "=r"(r) : "r"(x));
    return r;
}

// ---------------------------------------------------------------------------
__global__ void lam_kernel(const float* __restrict__ lq1, const float* __restrict__ lk1,
                           const float* __restrict__ lq2, const float* __restrict__ lk2) {
    int t = threadIdx.x;
    float v1 = lq1[t] * lk1[t];
    float v2 = lq2[t] * lk2[t];
    #pragma unroll
    for (int o = 16; o; o >>= 1) {
        v1 += __shfl_xor_sync(0xffffffffu, v1, o);
        v2 += __shfl_xor_sync(0xffffffffu, v2, o);
    }
    __shared__ float s1[4], s2[4];
    if ((t & 31) == 0) { s1[t >> 5] = v1; s2[t >> 5] = v2; }
    __syncthreads();
    if (t == 0) {
        float a = s1[0] + s1[1] + s1[2] + s1[3];
        float b = s2[0] + s2[1] + s2[2] + s2[3];
        g_lam = expf(a) - expf(b) + 0.8f;
    }
}

// fp32 -> fp16: first half of grid converts q (scaled by 1/sqrt(D)*log2e), second k
__global__ void cvt_kernel(const float4* __restrict__ q, const float4* __restrict__ k,
                           uint2* __restrict__ qh, uint2* __restrict__ kh, float scale) {
    const int half = (int)(gridDim.x >> 1);
    int blk = blockIdx.x;
    const float4* src;
    uint2* dst;
    float sc;
    if (blk < half) { src = q; dst = qh; sc = scale; }
    else            { src = k; dst = kh; sc = 1.0f; blk -= half; }
    int i = blk * blockDim.x + threadIdx.x;
    float4 v = src[i];
    uint2 o;
    o.x = pack2(v.x * sc, v.y * sc);
    o.y = pack2(v.z * sc, v.w * sc);
    dst[i] = o;
}

// v[bh][s][d] fp32 -> g_vth[bh][d][s] fp16
__global__ void vtr_kernel(const float* __restrict__ v) {
    __shared__ float st[32][33];
    int sbase = blockIdx.x * 32, dbase = blockIdx.y * 32, bh = blockIdx.z;
    const float* src = v + (size_t)bh * S_ * D_;
    __half* dst = g_vth + (size_t)bh * (size_t)D_ * S_;
    int x = threadIdx.x;
    for (int i = threadIdx.y; i < 32; i += 8)
        st[i][x] = src[(size_t)(sbase + i) * D_ + dbase + x];
    __syncthreads();
    for (int i = threadIdx.y; i < 32; i += 8)
        dst[(size_t)(dbase + i) * S_ + sbase + x] = __float2half(st[x][i]);
}

// ---------------------------------------------------------------------------
// fp16 mma flash attention, ghostmax. exp via ex2.approx.f16x2 (log2e folded
// into Q scale); row sums come out of the tensor core via a ones-row in Vt.
// ---------------------------------------------------------------------------
__global__ __launch_bounds__(NT, 1)
void attn_kernel() {
    extern __shared__ __half smh[];
    const uint32_t sb = smem_u32(smh);
    const int tid = threadIdx.x, lane = tid & 31, warp = tid >> 5;
    const int g = lane >> 2, t = lane & 3;
    const int qt = (int)gridDim.x - 1 - (int)blockIdx.x;  // heavy tiles first
    const int h2 = blockIdx.y, b = blockIdx.z;
    const int qbase = qt * BQ;
    const int row_lo = qbase + warp * 16 + g;
    const int row_hi = row_lo + 8;
    const int rowmin = qbase + warp * 16;
    const int rowmax = rowmin + 15;
    const size_t baseQ  = ((size_t)b * H2_ + h2) * S_ * D_;
    const size_t baseVT = ((size_t)b * H_ + (h2 >> 1)) * (size_t)D_ * S_;

    const int rowsel = (lane & 7) + ((lane >> 4) << 3);
    const uint32_t koff = ((lane >> 3) & 1) * 16;
    // address for the l-block (Vt rows 128-135) ldmatrix.x2
    const uint32_t eoff = (uint32_t)((128 + (lane & 7)) * 144) + koff;

    // init ones/zero rows of both V buffers (rows 128..135)
    {
        uint32_t* vb = (uint32_t*)(smh + OFF_V);
        // 2 stages * 8 rows * 36 u32 = 576 words
        for (int i = tid; i < 576; i += NT) {
            int stg = i / 288, r = (i % 288) / 36, c = i % 36;
            vb[(size_t)stg * (VSTRIDE / 2) + (128 + r) * 36 + c] =
                (r == 0) ? 0x3C003C00u : 0u;  // row 128 = 1.0h pairs
        }
    }

    // ---- Q A-fragments in registers
    uint32_t aq[8][4];
    {
        const __half* Qlo = g_qh + baseQ + (size_t)row_lo * D_;
        const __half* Qhi = g_qh + baseQ + (size_t)row_hi * D_;
        #pragma unroll
        for (int ks = 0; ks < 8; ks++) {
            aq[ks][0] = *(const uint32_t*)(Qlo + ks * 16 + 2 * t);
            aq[ks][1] = *(const uint32_t*)(Qhi + ks * 16 + 2 * t);
            aq[ks][2] = *(const uint32_t*)(Qlo + ks * 16 + 2 * t + 8);
            aq[ks][3] = *(const uint32_t*)(Qhi + ks * 16 + 2 * t + 8);
        }
    }

    const int nsteps = 2 * (qt + 1);

    auto issue = [&](int jt, int buf) {
        const __half* ksrc = g_kh + baseQ + (size_t)jt * BK * D_;
        uint32_t kdst = sb + (OFF_K + buf * KSTRIDE) * 2;
        #pragma unroll
        for (int i = 0; i < 4; i++) {
            int idx = tid + i * NT;
            int r = idx >> 4, c = idx & 15;
            CP16(kdst + r * 272 + c * 16, ksrc + r * 128 + c * 8);
        }
        const __half* vsrc = g_vth + baseVT + jt * BK;
        uint32_t vdst = sb + (OFF_V + buf * VSTRIDE) * 2;
        #pragma unroll
        for (int i = 0; i < 4; i++) {
            int idx = tid + i * NT;
            int r = idx >> 3, c = idx & 7;
            CP16(vdst + r * 144 + c * 16, vsrc + (size_t)r * S_ + c * 8);
        }
        CP_COMMIT();
    };

    issue(0, 0);

    float o[16][4];
    #pragma unroll
    for (int i = 0; i < 16; i++)
        #pragma unroll
        for (int j = 0; j < 4; j++) o[i][j] = 0.0f;
    float oe[4] = {0.0f, 0.0f, 0.0f, 0.0f};  // l accumulator block (col 128)

    for (int jt = 0; jt < nsteps; ++jt) {
        const int buf = jt & 1;
        __syncthreads();
        if (jt + 1 < nsteps) {
            issue(jt + 1, buf ^ 1);
            CP_WAIT(1);
        } else {
            CP_WAIT(0);
        }
        __syncthreads();

        if (jt * BK <= rowmax) {
            // ---- GEMM1: S = Q @ K^T (S in log2 domain)
            float s[8][4];
            #pragma unroll
            for (int i = 0; i < 8; i++)
                #pragma unroll
                for (int j = 0; j < 4; j++) s[i][j] = 0.0f;

            const uint32_t kmb = sb + (OFF_K + buf * KSTRIDE) * 2 + rowsel * 272 + koff;
            #pragma unroll
            for (int ks = 0; ks < 8; ks++) {
                #pragma unroll
                for (int np = 0; np < 4; np++) {
                    uint32_t b0, b1, b2, b3;
                    LDSM4(b0, b1, b2, b3, kmb + np * (16 * 272) + ks * 32);
                    mma16(s[2 * np],     aq[ks][0], aq[ks][1], aq[ks][2], aq[ks][3], b0, b1);
                    mma16(s[2 * np + 1], aq[ks][0], aq[ks][1], aq[ks][2], aq[ks][3], b2, b3);
                }
            }

            // ---- ghostmax numerators: P = exp2(S) in fp16x2 (A-frag layout)
            uint32_t pe[8][2];
            if (jt * BK + (BK - 1) <= rowmin) {  // fully unmasked tile
                #pragma unroll
                for (int nt = 0; nt < 8; nt++) {
                    pe[nt][0] = h2exp2(pack2(s[nt][0], s[nt][1]));
                    pe[nt][1] = h2exp2(pack2(s[nt][2], s[nt][3]));
                }
            } else {
                #pragma unroll
                for (int nt = 0; nt < 8; nt++) {
                    int c0 = jt * BK + nt * 8 + 2 * t;
                    float m0 = (c0     <= row_lo) ? s[nt][0] : -65000.0f;
                    float m1 = (c0 + 1 <= row_lo) ? s[nt][1] : -65000.0f;
                    float m2 = (c0     <= row_hi) ? s[nt][2] : -65000.0f;
                    float m3 = (c0 + 1 <= row_hi) ? s[nt][3] : -65000.0f;
                    pe[nt][0] = h2exp2(pack2(m0, m1));
                    pe[nt][1] = h2exp2(pack2(m2, m3));
                }
            }

            // ---- GEMM2: O += P @ V ; extra n-block (Vt ones row) -> row sums
            const uint32_t vmb = sb + (OFF_V + buf * VSTRIDE) * 2 + rowsel * 144 + koff;
            const uint32_t vme = sb + (OFF_V + buf * VSTRIDE) * 2 + eoff;
            #pragma unroll
            for (int j2 = 0; j2 < 4; j2++) {
                uint32_t a0 = pe[2 * j2][0];
                uint32_t a1 = pe[2 * j2][1];
                uint32_t a2 = pe[2 * j2 + 1][0];
                uint32_t a3 = pe[2 * j2 + 1][1];
                #pragma unroll
                for (int np = 0; np < 8; np++) {
                    uint32_t b0, b1, b2, b3;
                    LDSM4(b0, b1, b2, b3, vmb + np * (16 * 144) + j2 * 32);
                    mma16(o[2 * np],     a0, a1, a2, a3, b0, b1);
                    mma16(o[2 * np + 1], a0, a1, a2, a3, b2, b3);
                }
                uint32_t e0, e1;
                LDSM2(e0, e1, vme + j2 * 32);
                mma16(oe, a0, a1, a2, a3, e0, e1);
            }
        }
    }

    // l lives at col 128 -> thread t=0's oe[0]/oe[2]; broadcast within quad
    float l_lo = __shfl_sync(0xffffffffu, oe[0], lane & ~3);
    float l_hi = __shfl_sync(0xffffffffu, oe[2], lane & ~3);
    const float inv_lo = 1.0f / (l_lo + 1.0f);
    const float inv_hi = 1.0f / (l_hi + 1.0f);

    float* olo = g_o + baseQ + (size_t)row_lo * D_;
    float* ohi = g_o + baseQ + (size_t)row_hi * D_;
    #pragma unroll
    for (int nt = 0; nt < 16; nt++) {
        int c = nt * 8 + 2 * t;
        *(float2*)(olo + c) = make_float2(o[nt][0] * inv_lo, o[nt][1] * inv_lo);
        *(float2*)(ohi + c) = make_float2(o[nt][2] * inv_hi, o[nt][3] * inv_hi);
    }
}

// ---------------------------------------------------------------------------
// GroupNorm over x = o1 - lam*o2 per (b,h)  (float4 vectorized)
// ---------------------------------------------------------------------------
__global__ void gn_partial() {
    const int slice = blockIdx.x;
    const int bh = blockIdx.y;
    const int b = bh >> 3, h = bh & 7;
    const float lam = g_lam;
    const float4* o1 = (const float4*)(g_o + ((size_t)b * H2_ + 2 * h) * S_ * D_);
    const float4* o2 = o1 + (size_t)S_ * D_ / 4;
    double s = 0.0, s2 = 0.0;
    #pragma unroll
    for (int i = 0; i < 8; i++) {
        int idx = slice * 2048 + threadIdx.x + i * 256;
        float4 a = o1[idx], c = o2[idx];
        float x0 = a.x - lam * c.x, x1 = a.y - lam * c.y;
        float x2 = a.z - lam * c.z, x3 = a.w - lam * c.w;
        s += (double)x0 + (double)x1 + (double)x2 + (double)x3;
        s2 += (double)x0 * x0 + (double)x1 * x1 + (double)x2 * x2 + (double)x3 * x3;
    }
    #pragma unroll
    for (int o = 16; o; o >>= 1) {
        s  += __shfl_xor_sync(0xffffffffu, s, o);
        s2 += __shfl_xor_sync(0xffffffffu, s2, o);
    }
    __shared__ double rs[8], rs2[8];
    if ((threadIdx.x & 31) == 0) { rs[threadIdx.x >> 5] = s; rs2[threadIdx.x >> 5] = s2; }
    __syncthreads();
    if (threadIdx.x == 0) {
        double a = 0.0, c = 0.0;
        #pragma unroll
        for (int i = 0; i < 8; i++) { a += rs[i]; c += rs2[i]; }
        g_part[bh * 32 + slice] = make_double2(a, c);
    }
}

__global__ void gn_finalize() {
    const int bh = blockIdx.x;
    const int t = threadIdx.x;
    double2 p = g_part[bh * 32 + t];
    double s = p.x, s2 = p.y;
    #pragma unroll
    for (int o = 16; o; o >>= 1) {
        s  += __shfl_xor_sync(0xffffffffu, s, o);
        s2 += __shfl_xor_sync(0xffffffffu, s2, o);
    }
    if (t == 0) {
        const double N = (double)S_ * D_;
        double mean = s / N;
        double var = s2 / N - mean * mean;
        float rstd = (float)(1.0 / sqrt(var + 1e-5));
        g_stats[bh] = make_float2((float)mean, rstd);
    }
}

__global__ void gn_apply(const float* __restrict__ gw, const float* __restrict__ gb,
                         float* __restrict__ out) {
    size_t i4 = (size_t)blockIdx.x * blockDim.x + threadIdx.x;
    size_t e = i4 * 4;
    int t = (int)(e & 2047);
    int c = (int)((e >> 11) & 1023);
    int b = (int)(e >> 21);
    int h = c >> 7, cl = c & 127;
    int s = cl * 16 + (t >> 7), d = t & 127;
    const float lam = g_lam;
    float2 st = g_stats[b * 8 + h];
    size_t off = (((size_t)b * H2_ + 2 * h) * S_ + s) * D_ + d;
    float4 a = *(const float4*)(g_o + off);
    float4 cc = *(const float4*)(g_o + off + (size_t)S_ * D_);
    float wgt = 0.2f * st.y * gw[c];
    float bias = 0.2f * (gb[c] - st.x * st.y * gw[c]);
    float4 r;
    r.x = (a.x - lam * cc.x) * wgt + bias;
    r.y = (a.y - lam * cc.y) * wgt + bias;
    r.z = (a.z - lam * cc.z) * wgt + bias;
    r.w = (a.w - lam * cc.w) * wgt + bias;
    *(float4*)(out + e) = r;
}

// ---------------------------------------------------------------------------
extern "C" void kernel_launch(void* const* d_in, const int* in_sizes, int n_in,
                              void* d_out, int out_size) {
    const float* q   = (const float*)d_in[0];
    const float* k   = (const float*)d_in[1];
    const float* v   = (const float*)d_in[2];
    const float* lq1 = (const float*)d_in[3];
    const float* lk1 = (const float*)d_in[4];
    const float* lq2 = (const float*)d_in[5];
    const float* lk2 = (const float*)d_in[6];
    const float* gw  = (const float*)d_in[7];
    const float* gb  = (const float*)d_in[8];
    float* out = (float*)d_out;

    const int smem = SMH * 2;  // 73984 B
    cudaFuncSetAttribute(attn_kernel, cudaFuncAttributeMaxDynamicSharedMemorySize, smem);

    __half* qh; cudaGetSymbolAddress((void**)&qh, g_qh);
    __half* kh; cudaGetSymbolAddress((void**)&kh, g_kh);

    lam_kernel<<<1, 128>>>(lq1, lk1, lq2, lk2);
    // 1/sqrt(128) * log2(e): S comes out in log2 domain for ex2
    const float scaling = 0.12751743329705586f;
    cvt_kernel<<<16384, 256>>>((const float4*)q, (const float4*)k,
                               (uint2*)qh, (uint2*)kh, scaling);
    vtr_kernel<<<dim3(S_ / 32, D_ / 32, B_ * H_), dim3(32, 8)>>>(v);
    attn_kernel<<<dim3(S_ / BQ, H2_, B_), NT, smem>>>();
    gn_partial<<<dim3(32, 16), 256>>>();
    gn_finalize<<<16, 32>>>();
    gn_apply<<<4096, 256>>>(gw, gb, out);
}

// round 9
// speedup vs baseline: 1.4268x; 1.4268x over previous
#include <cuda_runtime.h>
#include <cuda_fp16.h>
#include <cstdint>
#include <math.h>

#define B_  2
#define H2_ 16
#define H_  8
#define S_  2048
#define D_  128
#define BQ  64
#define BK  64
#define NT  128

// smem layout in __half units
#define KPITCH 136               // 272 B/row; ldmatrix row phase 4r mod 32 -> CF
#define VPITCH 72                // 144 B/row
#define OFF_K  0
#define KSTRIDE (64 * KPITCH)    // 8704 halves per buffer
#define OFF_V  (2 * KSTRIDE)     // 17408
#define VSTRIDE (128 * VPITCH)   // 9216
#define SMH    (OFF_V + 2 * VSTRIDE)  // 35840 halves = 71680 B

// device scratch
__device__ float   g_o[(size_t)B_ * H2_ * S_ * D_];
__device__ __half  g_qh[(size_t)B_ * H2_ * S_ * D_];
__device__ __half  g_kh[(size_t)B_ * H2_ * S_ * D_];
__device__ __half  g_vth[(size_t)B_ * H_ * D_ * S_];
__device__ double2 g_part[16 * 32];
__device__ float2  g_stats[16];
__device__ float   g_lam;

__device__ __forceinline__ uint32_t smem_u32(const void* p) {
    uint32_t a;
    asm("{ .reg .u64 t; cvta.to.shared.u64 t, %1; cvt.u32.u64 %0, t; }" : "=r"(a) : "l"(p));
    return a;
}

#define CP16(dst, src) \
    asm volatile("cp.async.cg.shared.global [%0], [%1], 16;" :: "r"(dst), "l"(src))
#define CP_COMMIT() asm volatile("cp.async.commit_group;" ::: "memory")
#define CP_WAIT(n)  asm volatile("cp.async.wait_group %0;" :: "n"(n) : "memory")

#define LDSM4(r0, r1, r2, r3, a) \
    asm volatile("ldmatrix.sync.aligned.m8n8.x4.shared.b16 {%0,%1,%2,%3}, [%4];" \
        : "=r"(r0), "=r"(r1), "=r"(r2), "=r"(r3) : "r"(a))

__device__ __forceinline__ void mma16(float c[4], uint32_t a0, uint32_t a1,
                                      uint32_t a2, uint32_t a3,
                                      uint32_t b0, uint32_t b1) {
    asm volatile(
        "mma.sync.aligned.m16n8k16.row.col.f32.f16.f16.f32 "
        "{%0,%1,%2,%3}, {%4,%5,%6,%7}, {%8,%9}, {%0,%1,%2,%3};"
        : "+f"(c[0]), "+f"(c[1]), "+f"(c[2]), "+f"(c[3])
        : "r"(a0), "r"(a1), "r"(a2), "r"(a3), "r"(b0), "r"(b1));
}

__device__ __forceinline__ uint32_t pack2(float lo, float hi) {
    __half2 h = __floats2half2_rn(lo, hi);
    return *(uint32_t*)&h;
}

// ---------------------------------------------------------------------------
__global__ void lam_kernel(const float* __restrict__ lq1, const float* __restrict__ lk1,
                           const float* __restrict__ lq2, const float* __restrict__ lk2) {
    int t = threadIdx.x;
    float v1 = lq1[t] * lk1[t];
    float v2 = lq2[t] * lk2[t];
    #pragma unroll
    for (int o = 16; o; o >>= 1) {
        v1 += __shfl_xor_sync(0xffffffffu, v1, o);
        v2 += __shfl_xor_sync(0xffffffffu, v2, o);
    }
    __shared__ float s1[4], s2[4];
    if ((t & 31) == 0) { s1[t >> 5] = v1; s2[t >> 5] = v2; }
    __syncthreads();
    if (t == 0) {
        float a = s1[0] + s1[1] + s1[2] + s1[3];
        float b = s2[0] + s2[1] + s2[2] + s2[3];
        g_lam = expf(a) - expf(b) + 0.8f;
    }
}

// fp32 -> fp16: first half of grid converts q (scaled), second half k
__global__ void cvt_kernel(const float4* __restrict__ q, const float4* __restrict__ k,
                           uint2* __restrict__ qh, uint2* __restrict__ kh, float scale) {
    const int half = (int)(gridDim.x >> 1);
    int blk = blockIdx.x;
    const float4* src;
    uint2* dst;
    float sc;
    if (blk < half) { src = q; dst = qh; sc = scale; }
    else            { src = k; dst = kh; sc = 1.0f; blk -= half; }
    int i = blk * blockDim.x + threadIdx.x;
    float4 v = src[i];
    uint2 o;
    o.x = pack2(v.x * sc, v.y * sc);
    o.y = pack2(v.z * sc, v.w * sc);
    dst[i] = o;
}

// v[bh][s][d] fp32 -> g_vth[bh][d][s] fp16
__global__ void vtr_kernel(const float* __restrict__ v) {
    __shared__ float st[32][33];
    int sbase = blockIdx.x * 32, dbase = blockIdx.y * 32, bh = blockIdx.z;
    const float* src = v + (size_t)bh * S_ * D_;
    __half* dst = g_vth + (size_t)bh * (size_t)D_ * S_;
    int x = threadIdx.x;
    for (int i = threadIdx.y; i < 32; i += 8)
        st[i][x] = src[(size_t)(sbase + i) * D_ + dbase + x];
    __syncthreads();
    for (int i = threadIdx.y; i < 32; i += 8)
        dst[(size_t)(dbase + i) * S_ + sbase + x] = __float2half(st[x][i]);
}

// ---------------------------------------------------------------------------
// fp16 mma flash attention with ghostmax. 128-thread CTAs, 3 CTAs/SM for
// issue co-tenancy. Q A-fragments in registers, B-fragments via ldmatrix.x4.
// ---------------------------------------------------------------------------
__global__ __launch_bounds__(NT, 3)
void attn_kernel() {
    extern __shared__ __half smh[];
    const uint32_t sb = smem_u32(smh);
    const int tid = threadIdx.x, lane = tid & 31, warp = tid >> 5;
    const int g = lane >> 2, t = lane & 3;
    const int qt = (int)gridDim.x - 1 - (int)blockIdx.x;  // heavy tiles first
    const int h2 = blockIdx.y, b = blockIdx.z;
    const int qbase = qt * BQ;
    const int row_lo = qbase + warp * 16 + g;
    const int row_hi = row_lo + 8;
    const int rowmax = qbase + warp * 16 + 15;
    const size_t baseQ  = ((size_t)b * H2_ + h2) * S_ * D_;
    const size_t baseVT = ((size_t)b * H_ + (h2 >> 1)) * (size_t)D_ * S_;

    const int rowsel = (lane & 7) + ((lane >> 4) << 3);
    const uint32_t koff = ((lane >> 3) & 1) * 16;

    // ---- Q A-fragments: load once into registers (32 regs/thread)
    uint32_t aq[8][4];
    {
        const __half* Qlo = g_qh + baseQ + (size_t)row_lo * D_;
        const __half* Qhi = g_qh + baseQ + (size_t)row_hi * D_;
        #pragma unroll
        for (int ks = 0; ks < 8; ks++) {
            aq[ks][0] = *(const uint32_t*)(Qlo + ks * 16 + 2 * t);
            aq[ks][1] = *(const uint32_t*)(Qhi + ks * 16 + 2 * t);
            aq[ks][2] = *(const uint32_t*)(Qlo + ks * 16 + 2 * t + 8);
            aq[ks][3] = *(const uint32_t*)(Qhi + ks * 16 + 2 * t + 8);
        }
    }

    const int nsteps = qt + 1;

    auto issue = [&](int jt, int buf) {
        const __half* ksrc = g_kh + baseQ + (size_t)jt * BK * D_;
        uint32_t kdst = sb + (OFF_K + buf * KSTRIDE) * 2;
        #pragma unroll
        for (int i = 0; i < 8; i++) {
            int idx = tid + i * NT;
            int r = idx >> 4, c = idx & 15;
            CP16(kdst + r * 272 + c * 16, ksrc + r * 128 + c * 8);
        }
        const __half* vsrc = g_vth + baseVT + jt * BK;
        uint32_t vdst = sb + (OFF_V + buf * VSTRIDE) * 2;
        #pragma unroll
        for (int i = 0; i < 8; i++) {
            int idx = tid + i * NT;
            int r = idx >> 3, c = idx & 7;
            CP16(vdst + r * 144 + c * 16, vsrc + (size_t)r * S_ + c * 8);
        }
        CP_COMMIT();
    };

    issue(0, 0);

    float o[16][4];
    #pragma unroll
    for (int i = 0; i < 16; i++)
        #pragma unroll
        for (int j = 0; j < 4; j++) o[i][j] = 0.0f;
    float l_lo = 0.0f, l_hi = 0.0f;

    for (int jt = 0; jt < nsteps; ++jt) {
        const int buf = jt & 1;
        __syncthreads();
        if (jt + 1 < nsteps) {
            issue(jt + 1, buf ^ 1);
            CP_WAIT(1);
        } else {
            CP_WAIT(0);
        }
        __syncthreads();

        if (jt * BK <= rowmax) {
            // ---- GEMM1: S = Q @ K^T
            float s[8][4];
            #pragma unroll
            for (int i = 0; i < 8; i++)
                #pragma unroll
                for (int j = 0; j < 4; j++) s[i][j] = 0.0f;

            const uint32_t kmb = sb + (OFF_K + buf * KSTRIDE) * 2 + rowsel * 272 + koff;
            #pragma unroll
            for (int ks = 0; ks < 8; ks++) {
                #pragma unroll
                for (int np = 0; np < 4; np++) {
                    uint32_t b0, b1, b2, b3;
                    LDSM4(b0, b1, b2, b3, kmb + np * (16 * 272) + ks * 32);
                    mma16(s[2 * np],     aq[ks][0], aq[ks][1], aq[ks][2], aq[ks][3], b0, b1);
                    mma16(s[2 * np + 1], aq[ks][0], aq[ks][1], aq[ks][2], aq[ks][3], b2, b3);
                }
            }

            // ---- ghostmax numerators + causal mask + row sums
            #pragma unroll
            for (int nt = 0; nt < 8; nt++) {
                int c0 = jt * BK + nt * 8 + 2 * t;
                float p0 = (c0     <= row_lo) ? __expf(s[nt][0]) : 0.0f;
                float p1 = (c0 + 1 <= row_lo) ? __expf(s[nt][1]) : 0.0f;
                float p2 = (c0     <= row_hi) ? __expf(s[nt][2]) : 0.0f;
                float p3 = (c0 + 1 <= row_hi) ? __expf(s[nt][3]) : 0.0f;
                s[nt][0] = p0; s[nt][1] = p1; s[nt][2] = p2; s[nt][3] = p3;
                l_lo += p0 + p1;
                l_hi += p2 + p3;
            }

            // ---- GEMM2: O += P @ V (C-frags feed A-frags directly)
            const uint32_t vmb = sb + (OFF_V + buf * VSTRIDE) * 2 + rowsel * 144 + koff;
            #pragma unroll
            for (int j2 = 0; j2 < 4; j2++) {
                uint32_t a0 = pack2(s[2 * j2][0],     s[2 * j2][1]);
                uint32_t a1 = pack2(s[2 * j2][2],     s[2 * j2][3]);
                uint32_t a2 = pack2(s[2 * j2 + 1][0], s[2 * j2 + 1][1]);
                uint32_t a3 = pack2(s[2 * j2 + 1][2], s[2 * j2 + 1][3]);
                #pragma unroll
                for (int np = 0; np < 8; np++) {
                    uint32_t b0, b1, b2, b3;
                    LDSM4(b0, b1, b2, b3, vmb + np * (16 * 144) + j2 * 32);
                    mma16(o[2 * np],     a0, a1, a2, a3, b0, b1);
                    mma16(o[2 * np + 1], a0, a1, a2, a3, b2, b3);
                }
            }
        }
    }

    // reduce l across quad, normalize, store
    l_lo += __shfl_xor_sync(0xffffffffu, l_lo, 1);
    l_lo += __shfl_xor_sync(0xffffffffu, l_lo, 2);
    l_hi += __shfl_xor_sync(0xffffffffu, l_hi, 1);
    l_hi += __shfl_xor_sync(0xffffffffu, l_hi, 2);
    const float inv_lo = 1.0f / (l_lo + 1.0f);
    const float inv_hi = 1.0f / (l_hi + 1.0f);

    float* olo = g_o + baseQ + (size_t)row_lo * D_;
    float* ohi = g_o + baseQ + (size_t)row_hi * D_;
    #pragma unroll
    for (int nt = 0; nt < 16; nt++) {
        int c = nt * 8 + 2 * t;
        *(float2*)(olo + c) = make_float2(o[nt][0] * inv_lo, o[nt][1] * inv_lo);
        *(float2*)(ohi + c) = make_float2(o[nt][2] * inv_hi, o[nt][3] * inv_hi);
    }
}

// ---------------------------------------------------------------------------
// GroupNorm over x = o1 - lam*o2 per (b,h)  (float4 vectorized)
// ---------------------------------------------------------------------------
__global__ void gn_partial() {
    const int slice = blockIdx.x;
    const int bh = blockIdx.y;
    const int b = bh >> 3, h = bh & 7;
    const float lam = g_lam;
    const float4* o1 = (const float4*)(g_o + ((size_t)b * H2_ + 2 * h) * S_ * D_);
    const float4* o2 = o1 + (size_t)S_ * D_ / 4;
    double s = 0.0, s2 = 0.0;
    #pragma unroll
    for (int i = 0; i < 8; i++) {
        int idx = slice * 2048 + threadIdx.x + i * 256;
        float4 a = o1[idx], c = o2[idx];
        float x0 = a.x - lam * c.x, x1 = a.y - lam * c.y;
        float x2 = a.z - lam * c.z, x3 = a.w - lam * c.w;
        s += (double)x0 + (double)x1 + (double)x2 + (double)x3;
        s2 += (double)x0 * x0 + (double)x1 * x1 + (double)x2 * x2 + (double)x3 * x3;
    }
    #pragma unroll
    for (int o = 16; o; o >>= 1) {
        s  += __shfl_xor_sync(0xffffffffu, s, o);
        s2 += __shfl_xor_sync(0xffffffffu, s2, o);
    }
    __shared__ double rs[8], rs2[8];
    if ((threadIdx.x & 31) == 0) { rs[threadIdx.x >> 5] = s; rs2[threadIdx.x >> 5] = s2; }
    __syncthreads();
    if (threadIdx.x == 0) {
        double a = 0.0, c = 0.0;
        #pragma unroll
        for (int i = 0; i < 8; i++) { a += rs[i]; c += rs2[i]; }
        g_part[bh * 32 + slice] = make_double2(a, c);
    }
}

__global__ void gn_finalize() {
    const int bh = blockIdx.x;
    const int t = threadIdx.x;
    double2 p = g_part[bh * 32 + t];
    double s = p.x, s2 = p.y;
    #pragma unroll
    for (int o = 16; o; o >>= 1) {
        s  += __shfl_xor_sync(0xffffffffu, s, o);
        s2 += __shfl_xor_sync(0xffffffffu, s2, o);
    }
    if (t == 0) {
        const double N = (double)S_ * D_;
        double mean = s / N;
        double var = s2 / N - mean * mean;
        float rstd = (float)(1.0 / sqrt(var + 1e-5));
        g_stats[bh] = make_float2((float)mean, rstd);
    }
}

__global__ void gn_apply(const float* __restrict__ gw, const float* __restrict__ gb,
                         float* __restrict__ out) {
    size_t i4 = (size_t)blockIdx.x * blockDim.x + threadIdx.x;
    size_t e = i4 * 4;
    int t = (int)(e & 2047);
    int c = (int)((e >> 11) & 1023);
    int b = (int)(e >> 21);
    int h = c >> 7, cl = c & 127;
    int s = cl * 16 + (t >> 7), d = t & 127;
    const float lam = g_lam;
    float2 st = g_stats[b * 8 + h];
    size_t off = (((size_t)b * H2_ + 2 * h) * S_ + s) * D_ + d;
    float4 a = *(const float4*)(g_o + off);
    float4 cc = *(const float4*)(g_o + off + (size_t)S_ * D_);
    float wgt = 0.2f * st.y * gw[c];
    float bias = 0.2f * (gb[c] - st.x * st.y * gw[c]);
    float4 r;
    r.x = (a.x - lam * cc.x) * wgt + bias;
    r.y = (a.y - lam * cc.y) * wgt + bias;
    r.z = (a.z - lam * cc.z) * wgt + bias;
    r.w = (a.w - lam * cc.w) * wgt + bias;
    *(float4*)(out + e) = r;
}

// ---------------------------------------------------------------------------
extern "C" void kernel_launch(void* const* d_in, const int* in_sizes, int n_in,
                              void* d_out, int out_size) {
    const float* q   = (const float*)d_in[0];
    const float* k   = (const float*)d_in[1];
    const float* v   = (const float*)d_in[2];
    const float* lq1 = (const float*)d_in[3];
    const float* lk1 = (const float*)d_in[4];
    const float* lq2 = (const float*)d_in[5];
    const float* lk2 = (const float*)d_in[6];
    const float* gw  = (const float*)d_in[7];
    const float* gb  = (const float*)d_in[8];
    float* out = (float*)d_out;

    const int smem = SMH * 2;  // 71680 B
    cudaFuncSetAttribute(attn_kernel, cudaFuncAttributeMaxDynamicSharedMemorySize, smem);

    __half* qh; cudaGetSymbolAddress((void**)&qh, g_qh);
    __half* kh; cudaGetSymbolAddress((void**)&kh, g_kh);

    lam_kernel<<<1, 128>>>(lq1, lk1, lq2, lk2);
    const float scaling = 0.08838834764831845f;
    cvt_kernel<<<16384, 256>>>((const float4*)q, (const float4*)k,
                               (uint2*)qh, (uint2*)kh, scaling);
    vtr_kernel<<<dim3(S_ / 32, D_ / 32, B_ * H_), dim3(32, 8)>>>(v);
    attn_kernel<<<dim3(S_ / BQ, H2_, B_), NT, smem>>>();
    gn_partial<<<dim3(32, 16), 256>>>();
    gn_finalize<<<16, 32>>>();
    gn_apply<<<4096, 256>>>(gw, gb, out);
}

// round 10
// speedup vs baseline: 1.4633x; 1.0255x over previous
#include <cuda_runtime.h>
#include <cuda_fp16.h>
#include <cstdint>
#include <math.h>

#define B_  2
#define H2_ 16
#define H_  8
#define S_  2048
#define D_  128
#define BQ  128
#define BK2 128
#define NT  256

// smem in __half units: 2-stage ring of (K[128s x 128d], Vt[128d x 128s]), pitch 136
#define PITCH 136                  // 272 B/row; ldmatrix phase 16r mod 128 -> CF
#define TSTRIDE (128 * PITCH)      // 17408 halves per tile
#define OFF_K  0
#define OFF_V  (2 * TSTRIDE)
#define SMH    (4 * TSTRIDE)       // 69632 halves = 139264 B

// device scratch
__device__ float   g_o[(size_t)B_ * H2_ * S_ * D_];
__device__ __half  g_qh[(size_t)B_ * H2_ * S_ * D_];
__device__ __half  g_kh[(size_t)B_ * H2_ * S_ * D_];
__device__ __half  g_vth[(size_t)B_ * H_ * D_ * S_];
__device__ double2 g_part[16 * 32];
__device__ float   g_lam;

__device__ __forceinline__ uint32_t smem_u32(const void* p) {
    uint32_t a;
    asm("{ .reg .u64 t; cvta.to.shared.u64 t, %1; cvt.u32.u64 %0, t; }" : "=r"(a) : "l"(p));
    return a;
}

#define CP16(dst, src) \
    asm volatile("cp.async.cg.shared.global [%0], [%1], 16;" :: "r"(dst), "l"(src))
#define CP_COMMIT() asm volatile("cp.async.commit_group;" ::: "memory")
#define CP_WAIT(n)  asm volatile("cp.async.wait_group %0;" :: "n"(n) : "memory")

#define LDSM4(r0, r1, r2, r3, a) \
    asm volatile("ldmatrix.sync.aligned.m8n8.x4.shared.b16 {%0,%1,%2,%3}, [%4];" \
        : "=r"(r0), "=r"(r1), "=r"(r2), "=r"(r3) : "r"(a))

__device__ __forceinline__ void mma16(float c[4], uint32_t a0, uint32_t a1,
                                      uint32_t a2, uint32_t a3,
                                      uint32_t b0, uint32_t b1) {
    asm volatile(
        "mma.sync.aligned.m16n8k16.row.col.f32.f16.f16.f32 "
        "{%0,%1,%2,%3}, {%4,%5,%6,%7}, {%8,%9}, {%0,%1,%2,%3};"
        : "+f"(c[0]), "+f"(c[1]), "+f"(c[2]), "+f"(c[3])
        : "r"(a0), "r"(a1), "r"(a2), "r"(a3), "r"(b0), "r"(b1));
}

__device__ __forceinline__ uint32_t pack2(float lo, float hi) {
    __half2 h = __floats2half2_rn(lo, hi);
    return *(uint32_t*)&h;
}

// ---------------------------------------------------------------------------
// fp32 -> fp16: first half of grid converts q (scaled), second half k
__global__ void cvt_kernel(const float4* __restrict__ q, const float4* __restrict__ k,
                           uint2* __restrict__ qh, uint2* __restrict__ kh, float scale) {
    const int half = (int)(gridDim.x >> 1);
    int blk = blockIdx.x;
    const float4* src;
    uint2* dst;
    float sc;
    if (blk < half) { src = q; dst = qh; sc = scale; }
    else            { src = k; dst = kh; sc = 1.0f; blk -= half; }
    int i = blk * blockDim.x + threadIdx.x;
    float4 v = src[i];
    uint2 o;
    o.x = pack2(v.x * sc, v.y * sc);
    o.y = pack2(v.z * sc, v.w * sc);
    dst[i] = o;
}

// v[bh][s][d] fp32 -> g_vth[bh][d][s] fp16 ; block (0,0,0) also computes lambda
__global__ void vtr_kernel(const float* __restrict__ v,
                           const float* __restrict__ lq1, const float* __restrict__ lk1,
                           const float* __restrict__ lq2, const float* __restrict__ lk2) {
    __shared__ float st[32][33];
    __shared__ float lr1[4], lr2[4];
    int sbase = blockIdx.x * 32, dbase = blockIdx.y * 32, bh = blockIdx.z;
    const float* src = v + (size_t)bh * S_ * D_;
    __half* dst = g_vth + (size_t)bh * (size_t)D_ * S_;
    int x = threadIdx.x;
    for (int i = threadIdx.y; i < 32; i += 8)
        st[i][x] = src[(size_t)(sbase + i) * D_ + dbase + x];
    __syncthreads();
    for (int i = threadIdx.y; i < 32; i += 8)
        dst[(size_t)(dbase + i) * S_ + sbase + x] = __float2half(st[x][i]);

    if (blockIdx.x == 0 && blockIdx.y == 0 && blockIdx.z == 0) {
        int t = threadIdx.y * 32 + threadIdx.x;
        if (t < 128) {
            float v1 = lq1[t] * lk1[t];
            float v2 = lq2[t] * lk2[t];
            #pragma unroll
            for (int o = 16; o; o >>= 1) {
                v1 += __shfl_xor_sync(0xffffffffu, v1, o);
                v2 += __shfl_xor_sync(0xffffffffu, v2, o);
            }
            if ((t & 31) == 0) { lr1[t >> 5] = v1; lr2[t >> 5] = v2; }
        }
        __syncthreads();
        if (t == 0) {
            float a = lr1[0] + lr1[1] + lr1[2] + lr1[3];
            float b = lr2[0] + lr2[1] + lr2[2] + lr2[3];
            g_lam = expf(a) - expf(b) + 0.8f;
        }
    }
}

// ---------------------------------------------------------------------------
// fp16 mma flash attention with ghostmax. 128-col supersteps (one barrier
// pair + one cp.async group per 128 cols), two 64-col compute passes reusing
// the same S registers. Diagonal blocks skipped (bit-exact zeros).
// ---------------------------------------------------------------------------
__global__ __launch_bounds__(NT, 1)
void attn_kernel() {
    extern __shared__ __half smh[];
    const uint32_t sb = smem_u32(smh);
    const int tid = threadIdx.x, lane = tid & 31, warp = tid >> 5;
    const int g = lane >> 2, t = lane & 3;
    const int qt = (int)gridDim.x - 1 - (int)blockIdx.x;  // heavy tiles first
    const int h2 = blockIdx.y, b = blockIdx.z;
    const int qbase = qt * BQ;
    const int row_lo = qbase + warp * 16 + g;
    const int row_hi = row_lo + 8;
    const int rowmin = qbase + warp * 16;
    const int rowmax = rowmin + 15;
    const size_t baseQ  = ((size_t)b * H2_ + h2) * S_ * D_;
    const size_t baseVT = ((size_t)b * H_ + (h2 >> 1)) * (size_t)D_ * S_;

    const int rowsel = (lane & 7) + ((lane >> 4) << 3);
    const uint32_t koff = ((lane >> 3) & 1) * 16;

    // ---- Q A-fragments: load once into registers (32 regs/thread)
    uint32_t aq[8][4];
    {
        const __half* Qlo = g_qh + baseQ + (size_t)row_lo * D_;
        const __half* Qhi = g_qh + baseQ + (size_t)row_hi * D_;
        #pragma unroll
        for (int ks = 0; ks < 8; ks++) {
            aq[ks][0] = *(const uint32_t*)(Qlo + ks * 16 + 2 * t);
            aq[ks][1] = *(const uint32_t*)(Qhi + ks * 16 + 2 * t);
            aq[ks][2] = *(const uint32_t*)(Qlo + ks * 16 + 2 * t + 8);
            aq[ks][3] = *(const uint32_t*)(Qhi + ks * 16 + 2 * t + 8);
        }
    }

    const int nsteps = qt + 1;  // supersteps of 128 cols

    auto issue = [&](int jt, int buf) {
        const __half* ksrc = g_kh + baseQ + (size_t)jt * BK2 * D_;
        uint32_t kdst = sb + (OFF_K + buf * TSTRIDE) * 2;
        #pragma unroll
        for (int i = 0; i < 8; i++) {
            int idx = tid + i * NT;
            int r = idx >> 4, c = idx & 15;
            CP16(kdst + r * 272 + c * 16, ksrc + r * 128 + c * 8);
        }
        const __half* vsrc = g_vth + baseVT + jt * BK2;
        uint32_t vdst = sb + (OFF_V + buf * TSTRIDE) * 2;
        #pragma unroll
        for (int i = 0; i < 8; i++) {
            int idx = tid + i * NT;
            int r = idx >> 4, c = idx & 15;
            CP16(vdst + r * 272 + c * 16, vsrc + (size_t)r * S_ + c * 8);
        }
        CP_COMMIT();
    };

    issue(0, 0);

    float o[16][4];
    #pragma unroll
    for (int i = 0; i < 16; i++)
        #pragma unroll
        for (int j = 0; j < 4; j++) o[i][j] = 0.0f;
    float l_lo = 0.0f, l_hi = 0.0f;

    for (int jt = 0; jt < nsteps; ++jt) {
        const int buf = jt & 1;
        __syncthreads();
        if (jt + 1 < nsteps) {
            issue(jt + 1, buf ^ 1);
            CP_WAIT(1);
        } else {
            CP_WAIT(0);
        }
        __syncthreads();

        const uint32_t kst = sb + (OFF_K + buf * TSTRIDE) * 2;
        const uint32_t vst = sb + (OFF_V + buf * TSTRIDE) * 2;

        #pragma unroll
        for (int pass = 0; pass < 2; ++pass) {
            const int cb = jt * BK2 + pass * 64;
            if (cb > rowmax) break;

            // ---- GEMM1: S = Q @ K^T (skip fully-masked 16-col blocks)
            float s[8][4];
            #pragma unroll
            for (int i = 0; i < 8; i++)
                #pragma unroll
                for (int j = 0; j < 4; j++) s[i][j] = 0.0f;

            const uint32_t kmb = kst + pass * (64 * 272) + rowsel * 272 + koff;
            #pragma unroll
            for (int np = 0; np < 4; np++) {
                if (cb + np * 16 <= rowmax) {
                    #pragma unroll
                    for (int ks = 0; ks < 8; ks++) {
                        uint32_t b0, b1, b2, b3;
                        LDSM4(b0, b1, b2, b3, kmb + np * (16 * 272) + ks * 32);
                        mma16(s[2 * np],     aq[ks][0], aq[ks][1], aq[ks][2], aq[ks][3], b0, b1);
                        mma16(s[2 * np + 1], aq[ks][0], aq[ks][1], aq[ks][2], aq[ks][3], b2, b3);
                    }
                }
            }

            // ---- ghostmax numerators + causal mask + row sums
            if (cb + 63 <= rowmin) {  // fully unmasked pass
                #pragma unroll
                for (int nt = 0; nt < 8; nt++) {
                    float p0 = __expf(s[nt][0]);
                    float p1 = __expf(s[nt][1]);
                    float p2 = __expf(s[nt][2]);
                    float p3 = __expf(s[nt][3]);
                    s[nt][0] = p0; s[nt][1] = p1; s[nt][2] = p2; s[nt][3] = p3;
                    l_lo += p0 + p1;
                    l_hi += p2 + p3;
                }
            } else {
                #pragma unroll
                for (int nt = 0; nt < 8; nt++) {
                    if (cb + nt * 8 <= rowmax) {
                        int c0 = cb + nt * 8 + 2 * t;
                        float p0 = (c0     <= row_lo) ? __expf(s[nt][0]) : 0.0f;
                        float p1 = (c0 + 1 <= row_lo) ? __expf(s[nt][1]) : 0.0f;
                        float p2 = (c0     <= row_hi) ? __expf(s[nt][2]) : 0.0f;
                        float p3 = (c0 + 1 <= row_hi) ? __expf(s[nt][3]) : 0.0f;
                        s[nt][0] = p0; s[nt][1] = p1; s[nt][2] = p2; s[nt][3] = p3;
                        l_lo += p0 + p1;
                        l_hi += p2 + p3;
                    } else {
                        s[nt][0] = 0.0f; s[nt][1] = 0.0f; s[nt][2] = 0.0f; s[nt][3] = 0.0f;
                    }
                }
            }

            // ---- GEMM2: O += P @ V (C-frags feed A-frags; skip dead k-blocks)
            const uint32_t vmb = vst + pass * 128 + rowsel * 272 + koff;
            #pragma unroll
            for (int j2 = 0; j2 < 4; j2++) {
                if (cb + j2 * 16 <= rowmax) {
                    uint32_t a0 = pack2(s[2 * j2][0],     s[2 * j2][1]);
                    uint32_t a1 = pack2(s[2 * j2][2],     s[2 * j2][3]);
                    uint32_t a2 = pack2(s[2 * j2 + 1][0], s[2 * j2 + 1][1]);
                    uint32_t a3 = pack2(s[2 * j2 + 1][2], s[2 * j2 + 1][3]);
                    #pragma unroll
                    for (int np = 0; np < 8; np++) {
                        uint32_t b0, b1, b2, b3;
                        LDSM4(b0, b1, b2, b3, vmb + np * (16 * 272) + j2 * 32);
                        mma16(o[2 * np],     a0, a1, a2, a3, b0, b1);
                        mma16(o[2 * np + 1], a0, a1, a2, a3, b2, b3);
                    }
                }
            }
        }
    }

    // reduce l across quad, normalize, store
    l_lo += __shfl_xor_sync(0xffffffffu, l_lo, 1);
    l_lo += __shfl_xor_sync(0xffffffffu, l_lo, 2);
    l_hi += __shfl_xor_sync(0xffffffffu, l_hi, 1);
    l_hi += __shfl_xor_sync(0xffffffffu, l_hi, 2);
    const float inv_lo = 1.0f / (l_lo + 1.0f);
    const float inv_hi = 1.0f / (l_hi + 1.0f);

    float* olo = g_o + baseQ + (size_t)row_lo * D_;
    float* ohi = g_o + baseQ + (size_t)row_hi * D_;
    #pragma unroll
    for (int nt = 0; nt < 16; nt++) {
        int c = nt * 8 + 2 * t;
        *(float2*)(olo + c) = make_float2(o[nt][0] * inv_lo, o[nt][1] * inv_lo);
        *(float2*)(ohi + c) = make_float2(o[nt][2] * inv_hi, o[nt][3] * inv_hi);
    }
}

// ---------------------------------------------------------------------------
// GroupNorm over x = o1 - lam*o2 per (b,h)
// ---------------------------------------------------------------------------
__global__ void gn_partial() {
    const int slice = blockIdx.x;
    const int bh = blockIdx.y;
    const int b = bh >> 3, h = bh & 7;
    const float lam = g_lam;
    const float4* o1 = (const float4*)(g_o + ((size_t)b * H2_ + 2 * h) * S_ * D_);
    const float4* o2 = o1 + (size_t)S_ * D_ / 4;
    double s = 0.0, s2 = 0.0;
    #pragma unroll
    for (int i = 0; i < 8; i++) {
        int idx = slice * 2048 + threadIdx.x + i * 256;
        float4 a = o1[idx], c = o2[idx];
        float x0 = a.x - lam * c.x, x1 = a.y - lam * c.y;
        float x2 = a.z - lam * c.z, x3 = a.w - lam * c.w;
        s += (double)x0 + (double)x1 + (double)x2 + (double)x3;
        s2 += (double)x0 * x0 + (double)x1 * x1 + (double)x2 * x2 + (double)x3 * x3;
    }
    #pragma unroll
    for (int o = 16; o; o >>= 1) {
        s  += __shfl_xor_sync(0xffffffffu, s, o);
        s2 += __shfl_xor_sync(0xffffffffu, s2, o);
    }
    __shared__ double rs[8], rs2[8];
    if ((threadIdx.x & 31) == 0) { rs[threadIdx.x >> 5] = s; rs2[threadIdx.x >> 5] = s2; }
    __syncthreads();
    if (threadIdx.x == 0) {
        double a = 0.0, c = 0.0;
        #pragma unroll
        for (int i = 0; i < 8; i++) { a += rs[i]; c += rs2[i]; }
        g_part[bh * 32 + slice] = make_double2(a, c);
    }
}

// finalize (32-wide reduce of g_part) fused into apply
__global__ void gn_apply(const float* __restrict__ gw, const float* __restrict__ gb,
                         float* __restrict__ out) {
    __shared__ float2 stsh;
    const size_t e0 = (size_t)blockIdx.x * 1024;
    {
        int c_ = (int)((e0 >> 11) & 1023);
        int bh = ((int)(e0 >> 21)) * 8 + (c_ >> 7);
        if (threadIdx.x < 32) {
            double2 p = g_part[bh * 32 + threadIdx.x];
            double s = p.x, s2 = p.y;
            #pragma unroll
            for (int o = 16; o; o >>= 1) {
                s  += __shfl_xor_sync(0xffffffffu, s, o);
                s2 += __shfl_xor_sync(0xffffffffu, s2, o);
            }
            if (threadIdx.x == 0) {
                const double N = (double)S_ * D_;
                double mean = s / N;
                double var = s2 / N - mean * mean;
                stsh = make_float2((float)mean, (float)(1.0 / sqrt(var + 1e-5)));
            }
        }
    }
    __syncthreads();
    float2 st = stsh;
    size_t e = e0 + (size_t)threadIdx.x * 4;
    int t = (int)(e & 2047);
    int c = (int)((e >> 11) & 1023);
    int b = (int)(e >> 21);
    int h = c >> 7, cl = c & 127;
    int s = cl * 16 + (t >> 7), d = t & 127;
    const float lam = g_lam;
    size_t off = (((size_t)b * H2_ + 2 * h) * S_ + s) * D_ + d;
    float4 a = *(const float4*)(g_o + off);
    float4 cc = *(const float4*)(g_o + off + (size_t)S_ * D_);
    float wgt = 0.2f * st.y * gw[c];
    float bias = 0.2f * (gb[c] - st.x * st.y * gw[c]);
    float4 r;
    r.x = (a.x - lam * cc.x) * wgt + bias;
    r.y = (a.y - lam * cc.y) * wgt + bias;
    r.z = (a.z - lam * cc.z) * wgt + bias;
    r.w = (a.w - lam * cc.w) * wgt + bias;
    *(float4*)(out + e) = r;
}

// ---------------------------------------------------------------------------
extern "C" void kernel_launch(void* const* d_in, const int* in_sizes, int n_in,
                              void* d_out, int out_size) {
    const float* q   = (const float*)d_in[0];
    const float* k   = (const float*)d_in[1];
    const float* v   = (const float*)d_in[2];
    const float* lq1 = (const float*)d_in[3];
    const float* lk1 = (const float*)d_in[4];
    const float* lq2 = (const float*)d_in[5];
    const float* lk2 = (const float*)d_in[6];
    const float* gw  = (const float*)d_in[7];
    const float* gb  = (const float*)d_in[8];
    float* out = (float*)d_out;

    const int smem = SMH * 2;  // 139264 B
    cudaFuncSetAttribute(attn_kernel, cudaFuncAttributeMaxDynamicSharedMemorySize, smem);

    __half* qh; cudaGetSymbolAddress((void**)&qh, g_qh);
    __half* kh; cudaGetSymbolAddress((void**)&kh, g_kh);

    const float scaling = 0.08838834764831845f;
    cvt_kernel<<<16384, 256>>>((const float4*)q, (const float4*)k,
                               (uint2*)qh, (uint2*)kh, scaling);
    vtr_kernel<<<dim3(S_ / 32, D_ / 32, B_ * H_), dim3(32, 8)>>>(v, lq1, lk1, lq2, lk2);
    attn_kernel<<<dim3(S_ / BQ, H2_, B_), NT, smem>>>();
    gn_partial<<<dim3(32, 16), 256>>>();
    gn_apply<<<4096, 256>>>(gw, gb, out);
}